// round 14
// baseline (speedup 1.0000x reference)
#include <cuda_runtime.h>
#include <cuda_fp16.h>
#include <math.h>
#include <cstdint>

// Problem constants
constexpr int Bc = 8;
constexpr int Sc = 512;
constexpr int Ec = 1024;
constexpr int Hc = 16;
constexpr int Dc = 64;
constexpr int Mrows = Bc * Sc;   // 4096

// Scratch (static device arrays: allocation-free). All fp16.
__device__ __half g_Q[(size_t)Mrows * Ec];
__device__ __half g_K[(size_t)Mrows * Ec];
__device__ __half g_V[(size_t)Mrows * Ec];
__device__ __half g_ctx[(size_t)Mrows * Ec];
__device__ __half g_cxq[(size_t)Mrows * Ec];
__device__ __half g_cxk[(size_t)Mrows * Ec];
__device__ __half g_cxv[(size_t)Mrows * Ec];
__device__ __half g_cwq[(size_t)Ec * Ec];
__device__ __half g_cwk[(size_t)Ec * Ec];
__device__ __half g_cwv[(size_t)Ec * Ec];
__device__ __half g_cwo[(size_t)Ec * Ec];

// ---------------------------------------------------------------------------
// helpers
// ---------------------------------------------------------------------------
__device__ __forceinline__ uint32_t s2u(const void* p) {
    uint32_t a;
    asm("{ .reg .u64 t; cvta.to.shared.u64 t, %1; cvt.u32.u64 %0, t; }"
        : "=r"(a) : "l"(p));
    return a;
}

__device__ __forceinline__ void cp_async16(uint32_t saddr, const void* gaddr) {
    asm volatile("cp.async.cg.shared.global [%0], [%1], 16;" :: "r"(saddr), "l"(gaddr));
}
#define CP_COMMIT() asm volatile("cp.async.commit_group;" ::: "memory")
#define CP_WAIT(n)  asm volatile("cp.async.wait_group %0;" :: "n"(n) : "memory")

// pack two fp32 -> half2 (lo = first arg in low 16 bits)
__device__ __forceinline__ uint32_t pack_h2(float lo, float hi) {
    uint32_t r;
    asm("cvt.rn.f16x2.f32 %0, %1, %2;" : "=r"(r) : "f"(hi), "f"(lo));
    return r;
}

__device__ __forceinline__ void mma_f16(float* d, const uint32_t* a, const uint32_t* b) {
    asm volatile(
        "mma.sync.aligned.m16n8k16.row.col.f32.f16.f16.f32 "
        "{%0,%1,%2,%3}, {%4,%5,%6,%7}, {%8,%9}, {%0,%1,%2,%3};"
        : "+f"(d[0]), "+f"(d[1]), "+f"(d[2]), "+f"(d[3])
        : "r"(a[0]), "r"(a[1]), "r"(a[2]), "r"(a[3]), "r"(b[0]), "r"(b[1]));
}

__device__ __forceinline__ void ldsm4(uint32_t* r, const void* smem_ptr) {
    uint32_t a = s2u(smem_ptr);
    asm volatile("ldmatrix.sync.aligned.m8n8.x4.shared.b16 {%0,%1,%2,%3}, [%4];"
                 : "=r"(r[0]), "=r"(r[1]), "=r"(r[2]), "=r"(r[3]) : "r"(a));
}
__device__ __forceinline__ void ldsm4t(uint32_t* r, const void* smem_ptr) {
    uint32_t a = s2u(smem_ptr);
    asm volatile("ldmatrix.sync.aligned.m8n8.x4.trans.shared.b16 {%0,%1,%2,%3}, [%4];"
                 : "=r"(r[0]), "=r"(r[1]), "=r"(r[2]), "=r"(r[3]) : "r"(a));
}

// ---------------------------------------------------------------------------
// fused fp32 -> fp16 pre-pass for all 7 tensors (grid.y selects); 32B/thread
// ---------------------------------------------------------------------------
__global__ void cvt_all(const float* i0, const float* i1, const float* i2,
                        const float* i3, const float* i4, const float* i5,
                        const float* i6,
                        __half* o0, __half* o1, __half* o2, __half* o3,
                        __half* o4, __half* o5, __half* o6,
                        int nx8, int nw8) {
    const int y = blockIdx.y;
    const float* in;
    __half* out;
    int n8;
    switch (y) {
        case 0: in = i0; out = o0; n8 = nx8; break;
        case 1: in = i1; out = o1; n8 = nx8; break;
        case 2: in = i2; out = o2; n8 = nx8; break;
        case 3: in = i3; out = o3; n8 = nw8; break;
        case 4: in = i4; out = o4; n8 = nw8; break;
        case 5: in = i5; out = o5; n8 = nw8; break;
        default: in = i6; out = o6; n8 = nw8; break;
    }
    int i = blockIdx.x * blockDim.x + threadIdx.x;
    if (i >= n8) return;
    float4 v0 = ((const float4*)in)[2 * i];
    float4 v1 = ((const float4*)in)[2 * i + 1];
    uint4 r;
    r.x = pack_h2(v0.x, v0.y);
    r.y = pack_h2(v0.z, v0.w);
    r.z = pack_h2(v1.x, v1.y);
    r.w = pack_h2(v1.z, v1.w);
    ((uint4*)out)[i] = r;
}

// ---------------------------------------------------------------------------
// fp16 HMMA GEMM (R12 config): CTA 128x128, 128 threads (2x2 warps), warp tile
// 64x64, BK=32 halfs, 4-stage cp.async, pitch-40-half smem.
// mode 0: rope+l2norm+temp scatter -> half (Q)
// mode 1: rope+l2norm scatter -> half (K)
// mode 2: bias scatter -> half (V)
// mode 3: plain fp32 row-major (final out)
// ---------------------------------------------------------------------------
constexpr int BKH = 32;                    // halfs per chunk
constexpr int PITCHH = 40;                 // halfs (80B rows, ldsm conflict-free)
constexpr int STAGES = 4;
constexpr int TILE_H = 128 * PITCHH;       // 5120 halfs per tile
constexpr int STAGE_H = 2 * TILE_H;        // 10240
constexpr int NCH = Ec / BKH;              // 32
constexpr int SMEM_GEMM = STAGES * STAGE_H * 2;   // 81920 B

__device__ __forceinline__
void gemm_body(const __half* __restrict__ A, const __half* __restrict__ W,
               const float* __restrict__ bias, void* __restrict__ outv,
               int mode, const float* __restrict__ cosT,
               const float* __restrict__ sinT, float scale, __half* sm)
{
    const int tid = threadIdx.x;
    const int lane = tid & 31;
    const int wid = tid >> 5;
    const int warp_m = wid >> 1;          // 0..1
    const int warp_n = wid & 1;           // 0..1
    const int g = lane >> 2;
    const int t = lane & 3;
    const int m0 = blockIdx.y * 128;
    const int n0 = blockIdx.x * 128;

    // ldmatrix lane address components (no-trans for both A and B)
    const int aRow = warp_m * 64 + (lane & 15);                  // + mt*16
    const int aKoff = (lane >> 4) * 8;
    const int bN = warp_n * 64 + (lane & 7) + (lane >> 4) * 8;   // + pair*16
    const int bKoff = ((lane >> 3) & 1) * 8;

    float d[4][8][4];
    #pragma unroll
    for (int i = 0; i < 4; i++)
        #pragma unroll
        for (int j = 0; j < 8; j++)
            #pragma unroll
            for (int k = 0; k < 4; k++) d[i][j][k] = 0.f;

    const __half* gA0 = A + (size_t)m0 * Ec;
    const __half* gW0 = W + (size_t)n0 * Ec;

    auto load_stage = [&](int c) {
        __half* As = sm + (c % STAGES) * STAGE_H;
        __half* Bs = As + TILE_H;
        const __half* gA = gA0 + c * BKH;
        const __half* gW = gW0 + c * BKH;
        #pragma unroll
        for (int i = 0; i < 4; i++) {
            const int idx = tid + i * 128;       // 0..511
            const int row = idx >> 2, seg = idx & 3;
            cp_async16(s2u(As + row * PITCHH + seg * 8),
                       gA + (size_t)row * Ec + seg * 8);
            cp_async16(s2u(Bs + row * PITCHH + seg * 8),
                       gW + (size_t)row * Ec + seg * 8);
        }
    };

    load_stage(0); CP_COMMIT();
    load_stage(1); CP_COMMIT();
    load_stage(2); CP_COMMIT();

    for (int c = 0; c < NCH; c++) {
        const int pend = (NCH - 1 - c < 2) ? (NCH - 1 - c) : 2;
        if (pend == 2) { CP_WAIT(2); } else if (pend == 1) { CP_WAIT(1); }
        else { CP_WAIT(0); }
        __syncthreads();

        if (c + 3 < NCH) { load_stage(c + 3); CP_COMMIT(); }

        const __half* As = sm + (c % STAGES) * STAGE_H;
        const __half* Bs = As + TILE_H;

        #pragma unroll
        for (int ks = 0; ks < 2; ks++) {
            uint32_t a[4][4], b[4][4];
            #pragma unroll
            for (int mt = 0; mt < 4; mt++)
                ldsm4(a[mt], As + (aRow + mt * 16) * PITCHH + ks * 16 + aKoff);
            #pragma unroll
            for (int p = 0; p < 4; p++)
                ldsm4(b[p], Bs + (bN + p * 16) * PITCHH + ks * 16 + bKoff);
            #pragma unroll
            for (int mt = 0; mt < 4; mt++)
                #pragma unroll
                for (int p = 0; p < 4; p++) {
                    mma_f16(d[mt][2 * p + 0], a[mt], &b[p][0]);
                    mma_f16(d[mt][2 * p + 1], a[mt], &b[p][2]);
                }
        }
    }

    const uint32_t fullm = 0xffffffffu;

    if (mode <= 1) {
        __half* out = (__half*)outv;
        #pragma unroll
        for (int mt = 0; mt < 4; mt++) {
            const int m_g = m0 + warp_m * 64 + mt * 16 + g;
            const int s0 = m_g & (Sc - 1);
            const int s1 = (m_g + 8) & (Sc - 1);
            float2 r0v[8], r1v[8];
            float ss0 = 0.f, ss1 = 0.f;
            #pragma unroll
            for (int nt = 0; nt < 8; nt++) {
                const int ncol = n0 + warp_n * 64 + nt * 8 + 2 * t;
                const int j = (ncol & 63) >> 1;
                const float b0 = bias[ncol], b1 = bias[ncol + 1];
                const float c0 = cosT[s0 * 32 + j], sn0 = sinT[s0 * 32 + j];
                const float c1 = cosT[s1 * 32 + j], sn1 = sinT[s1 * 32 + j];
                {
                    const float x = d[mt][nt][0] + b0;
                    const float y = d[mt][nt][1] + b1;
                    const float rx = x * c0 - y * sn0;
                    const float ry = x * sn0 + y * c0;
                    ss0 += rx * rx + ry * ry;
                    r0v[nt] = make_float2(rx, ry);
                }
                {
                    const float x = d[mt][nt][2] + b0;
                    const float y = d[mt][nt][3] + b1;
                    const float rx = x * c1 - y * sn1;
                    const float ry = x * sn1 + y * c1;
                    ss1 += rx * rx + ry * ry;
                    r1v[nt] = make_float2(rx, ry);
                }
            }
            ss0 += __shfl_xor_sync(fullm, ss0, 1);
            ss0 += __shfl_xor_sync(fullm, ss0, 2);
            ss1 += __shfl_xor_sync(fullm, ss1, 1);
            ss1 += __shfl_xor_sync(fullm, ss1, 2);
            const float inv0 = scale / fmaxf(sqrtf(ss0), 1e-12f);
            const float inv1 = scale / fmaxf(sqrtf(ss1), 1e-12f);

            #pragma unroll
            for (int nt = 0; nt < 8; nt++) {
                const int ncol = n0 + warp_n * 64 + nt * 8 + 2 * t;
                const int hh = ncol >> 6, dd = ncol & (Dc - 1);
                {
                    const int bb = m_g >> 9;
                    *(uint32_t*)&out[((((size_t)bb * Hc + hh) * Sc + s0) << 6) + dd] =
                        pack_h2(r0v[nt].x * inv0, r0v[nt].y * inv0);
                }
                {
                    const int bb = (m_g + 8) >> 9;
                    *(uint32_t*)&out[((((size_t)bb * Hc + hh) * Sc + s1) << 6) + dd] =
                        pack_h2(r1v[nt].x * inv1, r1v[nt].y * inv1);
                }
            }
        }
    } else if (mode == 2) {
        __half* out = (__half*)outv;
        #pragma unroll
        for (int mt = 0; mt < 4; mt++) {
            #pragma unroll
            for (int nt = 0; nt < 8; nt++) {
                const int n = n0 + warp_n * 64 + nt * 8 + 2 * t;
                const float b0 = bias[n], b1 = bias[n + 1];
                #pragma unroll
                for (int half = 0; half < 2; half++) {
                    const int m = m0 + warp_m * 64 + mt * 16 + g + half * 8;
                    const int bb = m >> 9, ss = m & (Sc - 1);
                    const int hh = n >> 6, dd = n & (Dc - 1);
                    *(uint32_t*)&out[((((size_t)bb * Hc + hh) * Sc + ss) << 6) + dd] =
                        pack_h2(d[mt][nt][half * 2 + 0] + b0,
                                d[mt][nt][half * 2 + 1] + b1);
                }
            }
        }
    } else {
        float* out = (float*)outv;
        #pragma unroll
        for (int mt = 0; mt < 4; mt++) {
            #pragma unroll
            for (int nt = 0; nt < 8; nt++) {
                const int n = n0 + warp_n * 64 + nt * 8 + 2 * t;
                const float b0 = bias[n], b1 = bias[n + 1];
                #pragma unroll
                for (int half = 0; half < 2; half++) {
                    const int m = m0 + warp_m * 64 + mt * 16 + g + half * 8;
                    float2 v;
                    v.x = d[mt][nt][half * 2 + 0] + b0;
                    v.y = d[mt][nt][half * 2 + 1] + b1;
                    *(float2*)&out[(size_t)m * Ec + n] = v;
                }
            }
        }
    }
}

__global__ __launch_bounds__(128, 2)
void gemm_qkv(const __half* A0, const __half* A1, const __half* A2,
              const __half* W0, const __half* W1, const __half* W2,
              const float* b0, const float* b1, const float* b2,
              __half* o0, __half* o1, __half* o2,
              const float* cosT, const float* sinT, const float* tempPtr)
{
    extern __shared__ __half smh[];
    const int z = blockIdx.z;
    const __half* A = z == 0 ? A0 : z == 1 ? A1 : A2;
    const __half* W = z == 0 ? W0 : z == 1 ? W1 : W2;
    const float* bi = z == 0 ? b0 : z == 1 ? b1 : b2;
    __half* out = z == 0 ? o0 : z == 1 ? o1 : o2;
    const float scale = (z == 0) ? *tempPtr : 1.0f;
    gemm_body(A, W, bi, out, z, cosT, sinT, scale, smh);
}

__global__ __launch_bounds__(128, 2)
void gemm_out(const __half* __restrict__ A, const __half* __restrict__ W,
              const float* __restrict__ bias, float* __restrict__ out)
{
    extern __shared__ __half smh[];
    gemm_body(A, W, bias, out, 3, nullptr, nullptr, 1.0f, smh);
}

// ---------------------------------------------------------------------------
// fp16 flash attention: q-tile 128, 128 threads, warp owns 32 q-rows.
// Fixed-max softmax (|score| <= |temp|). K/V prefetched in 128-key PAIRS.
// Register diet: probs packed to half2 immediately after exp (frees the 64
// fp32 score regs before PV).
// smem: QT[128][72] | K[4][64][72] | V[4][64][72] = 92160 B
// ---------------------------------------------------------------------------
constexpr int APH = 72;                    // halfs (144B rows)
constexpr int QT_H = 128 * APH;            // 9216 halfs
constexpr int KV_H = 64 * APH;             // 4608 halfs
constexpr int SMEM_FLASH = (QT_H + 8 * KV_H) * 2;  // 92160 B

__global__ __launch_bounds__(128, 2)
void attn_flash(const __half* __restrict__ Q,
                const __half* __restrict__ K,
                const __half* __restrict__ V,
                __half* __restrict__ ctx,
                const float* __restrict__ tempPtr)
{
    extern __shared__ __half smh[];
    __half* QT = smh;
    __half* Kb = smh + QT_H;               // 4 chunk buffers
    __half* Vb = Kb + 4 * KV_H;            // 4 chunk buffers

    const int tid = threadIdx.x;
    const int lane = tid & 31;
    const int warp = tid >> 5;
    const int g = lane >> 2;
    const int t = lane & 3;
    const int qt = blockIdx.x;
    const int bh = blockIdx.y;
    const int bb = bh >> 4;
    const int hh = bh & 15;
    const size_t head_off = (size_t)bh * Sc * Dc;
    const float M = fabsf(*tempPtr);

    // ldmatrix lane components
    const int qRow = warp * 32 + (lane & 15);                    // + mt*16 (no-trans A)
    const int qKoff = (lane >> 4) * 8;
    const int kKey = (lane & 7) + (lane >> 4) * 8;               // + pair*16 (no-trans B)
    const int kDoff = ((lane >> 3) & 1) * 8;
    const int vKey = lane & 15;                                  // + kstep*16 (TRANS B)
    const int vDoff = (lane >> 4) * 8;                           // + dpair*16

    // ---- load Q tile [128][64] halfs ----
    {
        const __half* gQ = Q + head_off + (size_t)qt * 128 * Dc;
        for (int i = tid; i < 1024; i += 128) {
            const int r = i >> 3, s = i & 7;
            *(uint4*)&QT[r * APH + s * 8] = *(const uint4*)&gQ[r * Dc + s * 8];
        }
    }

    // prefetch a 128-key pair (chunks 2*pi, 2*pi+1) into chunk buffers
    auto load_pair = [&](int pi) {
        const int base = (pi & 1) * 2;
        const __half* gK = K + head_off + (size_t)pi * 128 * Dc;
        const __half* gV = V + head_off + (size_t)pi * 128 * Dc;
        #pragma unroll
        for (int i = 0; i < 8; i++) {
            const int idx = tid + i * 128;     // 0..1023
            const int r = idx >> 3, s = idx & 7;
            const int slot = base + (r >> 6);
            const int rr = r & 63;
            cp_async16(s2u(Kb + slot * KV_H + rr * APH + s * 8),
                       gK + (size_t)r * Dc + s * 8);
            cp_async16(s2u(Vb + slot * KV_H + rr * APH + s * 8),
                       gV + (size_t)r * Dc + s * 8);
        }
    };

    load_pair(0); CP_COMMIT();

    float run_s[2][2] = {{0.f, 0.f}, {0.f, 0.f}};
    float oacc[2][8][4];
    #pragma unroll
    for (int mt = 0; mt < 2; mt++)
        #pragma unroll
        for (int j = 0; j < 8; j++)
            #pragma unroll
            for (int k = 0; k < 4; k++) oacc[mt][j][k] = 0.f;

    const uint32_t fullm = 0xffffffffu;

    for (int pi = 0; pi < 4; pi++) {
        CP_WAIT(0);
        __syncthreads();     // pair pi ready; all warps done with pair pi-1

        if (pi < 3) { load_pair(pi + 1); CP_COMMIT(); }

        #pragma unroll
        for (int sub = 0; sub < 2; sub++) {
            const int slot = (pi & 1) * 2 + sub;
            const __half* Kc = Kb + slot * KV_H;
            const __half* Vc = Vb + slot * KV_H;

            // ---- QK^T + immediate exp+pack into half2 A-frags ----
            // ph[mt][kk][r]: A-fragment regs for PV (32 uint32 total)
            uint32_t ph[2][4][4];
            {
                float s[2][8][4];
                #pragma unroll
                for (int mt = 0; mt < 2; mt++)
                    #pragma unroll
                    for (int j = 0; j < 8; j++)
                        #pragma unroll
                        for (int k = 0; k < 4; k++) s[mt][j][k] = 0.f;

                #pragma unroll
                for (int ks = 0; ks < 4; ks++) {
                    uint32_t a[2][4], b[4][4];
                    #pragma unroll
                    for (int mt = 0; mt < 2; mt++)
                        ldsm4(a[mt], QT + (qRow + mt * 16) * APH + ks * 16 + qKoff);
                    #pragma unroll
                    for (int p = 0; p < 4; p++)
                        ldsm4(b[p], Kc + (kKey + p * 16) * APH + ks * 16 + kDoff);
                    #pragma unroll
                    for (int mt = 0; mt < 2; mt++)
                        #pragma unroll
                        for (int p = 0; p < 4; p++) {
                            mma_f16(s[mt][2 * p + 0], a[mt], &b[p][0]);
                            mma_f16(s[mt][2 * p + 1], a[mt], &b[p][2]);
                        }
                }

                // fixed-max softmax: exp, accumulate sums, pack -> releases s
                #pragma unroll
                for (int mt = 0; mt < 2; mt++)
                    #pragma unroll
                    for (int kk = 0; kk < 4; kk++) {
                        float p00 = __expf(s[mt][2 * kk][0] - M);
                        float p01 = __expf(s[mt][2 * kk][1] - M);
                        float p02 = __expf(s[mt][2 * kk][2] - M);
                        float p03 = __expf(s[mt][2 * kk][3] - M);
                        float p10 = __expf(s[mt][2 * kk + 1][0] - M);
                        float p11 = __expf(s[mt][2 * kk + 1][1] - M);
                        float p12 = __expf(s[mt][2 * kk + 1][2] - M);
                        float p13 = __expf(s[mt][2 * kk + 1][3] - M);
                        run_s[mt][0] += p00 + p01 + p10 + p11;
                        run_s[mt][1] += p02 + p03 + p12 + p13;
                        ph[mt][kk][0] = pack_h2(p00, p01);
                        ph[mt][kk][1] = pack_h2(p02, p03);
                        ph[mt][kk][2] = pack_h2(p10, p11);
                        ph[mt][kk][3] = pack_h2(p12, p13);
                    }
            }

            // ---- PV ----
            #pragma unroll
            for (int kk = 0; kk < 4; kk++) {
                #pragma unroll
                for (int p = 0; p < 4; p++) {
                    uint32_t b[4];
                    ldsm4t(b, Vc + (kk * 16 + vKey) * APH + p * 16 + vDoff);
                    #pragma unroll
                    for (int mt = 0; mt < 2; mt++) {
                        mma_f16(oacc[mt][2 * p + 0], ph[mt][kk], &b[0]);
                        mma_f16(oacc[mt][2 * p + 1], ph[mt][kk], &b[2]);
                    }
                }
            }
        }
    }

    // ---- reduce row sums across quad ----
    #pragma unroll
    for (int mt = 0; mt < 2; mt++)
        #pragma unroll
        for (int h = 0; h < 2; h++) {
            run_s[mt][h] += __shfl_xor_sync(fullm, run_s[mt][h], 1);
            run_s[mt][h] += __shfl_xor_sync(fullm, run_s[mt][h], 2);
        }

    // ---- epilogue ----
    #pragma unroll
    for (int mt = 0; mt < 2; mt++) {
        const float inv0 = 1.f / run_s[mt][0];
        const float inv1 = 1.f / run_s[mt][1];
        #pragma unroll
        for (int d8 = 0; d8 < 8; d8++) {
            const int dcol = d8 * 8 + 2 * t;
            {
                const int srow = qt * 128 + warp * 32 + mt * 16 + g;
                *(uint32_t*)&ctx[((size_t)bb * Sc + srow) * Ec + hh * Dc + dcol] =
                    pack_h2(oacc[mt][d8][0] * inv0, oacc[mt][d8][1] * inv0);
            }
            {
                const int srow = qt * 128 + warp * 32 + mt * 16 + g + 8;
                *(uint32_t*)&ctx[((size_t)bb * Sc + srow) * Ec + hh * Dc + dcol] =
                    pack_h2(oacc[mt][d8][2] * inv1, oacc[mt][d8][3] * inv1);
            }
        }
    }
}

// ---------------------------------------------------------------------------
extern "C" void kernel_launch(void* const* d_in, const int* in_sizes, int n_in,
                              void* d_out, int out_size)
{
    const float* x_q  = (const float*)d_in[0];
    const float* x_k  = (const float*)d_in[1];
    const float* x_v  = (const float*)d_in[2];
    const float* Wq   = (const float*)d_in[3];
    const float* bq   = (const float*)d_in[4];
    const float* Wk   = (const float*)d_in[5];
    const float* bk   = (const float*)d_in[6];
    const float* Wv   = (const float*)d_in[7];
    const float* bv   = (const float*)d_in[8];
    const float* Wo   = (const float*)d_in[9];
    const float* bo   = (const float*)d_in[10];
    const float* temp = (const float*)d_in[11];
    const float* cosT = (const float*)d_in[12];
    const float* sinT = (const float*)d_in[13];
    float* out = (float*)d_out;

    __half *pQ, *pK, *pV, *pC, *cxq, *cxk, *cxv, *cwq, *cwk, *cwv, *cwo;
    cudaGetSymbolAddress((void**)&pQ, g_Q);
    cudaGetSymbolAddress((void**)&pK, g_K);
    cudaGetSymbolAddress((void**)&pV, g_V);
    cudaGetSymbolAddress((void**)&pC, g_ctx);
    cudaGetSymbolAddress((void**)&cxq, g_cxq);
    cudaGetSymbolAddress((void**)&cxk, g_cxk);
    cudaGetSymbolAddress((void**)&cxv, g_cxv);
    cudaGetSymbolAddress((void**)&cwq, g_cwq);
    cudaGetSymbolAddress((void**)&cwk, g_cwk);
    cudaGetSymbolAddress((void**)&cwv, g_cwv);
    cudaGetSymbolAddress((void**)&cwo, g_cwo);

    cudaFuncSetAttribute(gemm_qkv,
                         cudaFuncAttributeMaxDynamicSharedMemorySize, SMEM_GEMM);
    cudaFuncSetAttribute(gemm_out,
                         cudaFuncAttributeMaxDynamicSharedMemorySize, SMEM_GEMM);
    cudaFuncSetAttribute(attn_flash,
                         cudaFuncAttributeMaxDynamicSharedMemorySize, SMEM_FLASH);

    const int nx8 = Mrows * Ec / 8;   // 512K
    const int nw8 = Ec * Ec / 8;      // 128K

    cvt_all<<<dim3((nx8 + 255) / 256, 7), 256>>>(
        x_q, x_k, x_v, Wq, Wk, Wv, Wo,
        cxq, cxk, cxv, cwq, cwk, cwv, cwo, nx8, nw8);

    gemm_qkv<<<dim3(Ec / 128, Mrows / 128, 3), 128, SMEM_GEMM>>>(
        cxq, cxk, cxv, cwq, cwk, cwv, bq, bk, bv, pQ, pK, pV,
        cosT, sinT, temp);

    attn_flash<<<dim3(4, Bc * Hc), 128, SMEM_FLASH>>>(pQ, pK, pV, pC, temp);

    gemm_out<<<dim3(Ec / 128, Mrows / 128), 128, SMEM_GEMM>>>(pC, cwo, bo, out);
}